// round 13
// baseline (speedup 1.0000x reference)
#include <cuda_runtime.h>
#include <cuda_fp16.h>
#include <mma.h>
#include <cstdint>

using namespace nvcuda;

// ---------------------------------------------------------------------------
// Problem constants
// ---------------------------------------------------------------------------
#define M_TOK   4096
#define K_IN    4096
#define N_OUT   11008
#define GROUPSZ 128

// GEMM tiling: 8 warps, warp tile 64x64 (grid 4M x 2N), 3-stage ring
#define BM      256
#define BN      128
#define BK      64
#define NITER   (K_IN / BK)        // 64
#define NTHREADS 256
#define NSTAGE  3

#define A_LD    72                 // 64 + 8 pad (halves)
#define B_LD    136                // 128 + 8 pad (halves)
#define C_LD    68                 // 64 + 4 pad (floats), epilogue staging

#define A_STAGE_BYTES (BM * A_LD * 2)      // 36864
#define B_STAGE_BYTES (BK * B_LD * 2)      // 17408
#define STAGE_BYTES   (A_STAGE_BYTES + B_STAGE_BYTES)   // 54272
#define SMEM_DYN      (NSTAGE * STAGE_BYTES)            // 162816 (1 CTA/SM)

// fp16 x scratch (no allocations allowed)
__device__ __half g_Xh[(size_t)M_TOK * K_IN];

// ---------------------------------------------------------------------------
// Kernel 0: convert x f32 -> f16 (harness materializes jax f16 as f32)
// ---------------------------------------------------------------------------
__global__ void convert_x_kernel(const float* __restrict__ x)
{
    size_t i = ((size_t)blockIdx.x * blockDim.x + threadIdx.x) * 4;
    if (i >= (size_t)M_TOK * K_IN) return;
    float4 v = *(const float4*)(x + i);
    *(__half2*)(g_Xh + i)     = __floats2half2_rn(v.x, v.y);
    *(__half2*)(g_Xh + i + 2) = __floats2half2_rn(v.z, v.w);
}

// ---------------------------------------------------------------------------
// helpers
// ---------------------------------------------------------------------------
__device__ __forceinline__ uint32_t smem_u32(const void* p) {
    uint32_t a;
    asm("{ .reg .u64 t; cvta.to.shared.u64 t, %1; cvt.u32.u64 %0, t; }"
        : "=r"(a) : "l"(p));
    return a;
}
__device__ __forceinline__ void cp_async16(uint32_t saddr, const void* gaddr) {
    asm volatile("cp.async.ca.shared.global [%0], [%1], 16;\n"
                 :: "r"(saddr), "l"(gaddr));
}
#define CP_COMMIT() asm volatile("cp.async.commit_group;\n" ::: "memory")
#define CP_WAIT2()  asm volatile("cp.async.wait_group 2;\n" ::: "memory")

// ---------------------------------------------------------------------------
// Fused 4-bit dequant + HMMA GEMM:  C[M,N] = X[M,K] * dequant(Q)[K,N] + bias
//
// qweight: [K/8, N] int32 nibbles pack K; qzeros: [G, N/8] nibbles pack N;
// scales: [G, N] f32 (fp16 values).
// Dequant in the PRODUCER phase (phase-separated from MMA issue; R12 showed
// consumer-side dequant starves the tensor pipe) via fp16 magic numbers:
// fp16(0x6400|q) = 1024+q exactly, (u-(1024+z))*s bit-exact.
//
// BM=256 x BN=128: per-output smem traffic is 21% lower than 128x128
// (fragment re-reads scale with warp-count per dim; 4Mx2N of 64x64 tiles).
// 3-stage ring, produce stage ks+2 while computing ks; commit-per-iter +
// wait_group(2) means the awaited cp.async group landed 2 stages ago.
// ---------------------------------------------------------------------------
__global__ void __launch_bounds__(NTHREADS, 1)
gemm_q4_kernel(const int* __restrict__ qweight,
               const int* __restrict__ qzeros,
               const float* __restrict__ scales,
               const float* __restrict__ bias,
               float* __restrict__ out)
{
    extern __shared__ __align__(16) char smem[];
    const uint32_t sbase = smem_u32(smem);

    const int tid  = threadIdx.x;
    const int warp = tid >> 5;
    const int lane = tid & 31;
    const int bm   = blockIdx.x * BM;   // M fastest: A + qweight stay L2-resident
    const int bn   = blockIdx.y * BN;

    // warp tile: 64x64.  warp grid 4(M) x 2(N)
    const int wm = (warp >> 1) * 64;
    const int wn = (warp & 1) * 64;

    const __half* Xb = g_Xh + (size_t)bm * K_IN;

    // ---- B dequant mapping: 1 kp row x 4 cols per thread ----
    const int n0  = (tid & 31) * 4;          // 0,4,...,124
    const int kp0 = tid >> 5;                // 0..7
    const int o   = bn + n0;

    wmma::fragment<wmma::accumulator, 16, 16, 16, float> acc[4][4];
    #pragma unroll
    for (int i = 0; i < 4; i++)
        #pragma unroll
        for (int j = 0; j < 4; j++)
            wmma::fill_fragment(acc[i][j], 0.0f);

    uint4   breg;             // qweight words: 4 cols of one kp row
    __half2 hz[2];            // (1024+z) pairs
    __half2 hs[2];            // scale pairs

    auto ldg_b = [&](int ks) {
        breg = *(const uint4*)(qweight + (size_t)(ks * 8 + kp0) * N_OUT + o);
    };
    auto ldg_consts = [&](int g) {
        uint32_t zw = (uint32_t)qzeros[(size_t)g * (N_OUT / 8) + (o >> 3)];
        uint32_t sh = (o & 7) * 4;      // 0 or 16
        uint32_t z0 = ((zw >> (sh + 0)) & 15u) + 1u + 0x6400u;
        uint32_t z1 = ((zw >> (sh + 4)) & 15u) + 1u + 0x6400u;
        uint32_t z2 = ((zw >> (sh + 8)) & 15u) + 1u + 0x6400u;
        uint32_t z3 = ((zw >> (sh + 12)) & 15u) + 1u + 0x6400u;
        uint32_t p01 = z0 | (z1 << 16), p23 = z2 | (z3 << 16);
        hz[0] = *(__half2*)&p01;
        hz[1] = *(__half2*)&p23;
        float4 s4 = *(const float4*)(scales + (size_t)g * N_OUT + o);
        hs[0] = __halves2half2(__float2half_rn(s4.x), __float2half_rn(s4.y));
        hs[1] = __halves2half2(__float2half_rn(s4.z), __float2half_rn(s4.w));
    };
    auto issue_a = [&](int ks, uint32_t abase) {
        const int k0 = ks * BK;
        #pragma unroll
        for (int i = 0; i < 8; i++) {
            int c = tid + NTHREADS * i;          // 0..2047
            int row = c >> 3, cc = c & 7;
            cp_async16(abase + (uint32_t)(row * A_LD + cc * 8) * 2,
                       Xb + (size_t)row * K_IN + k0 + cc * 8);
        }
    };
    auto store_b = [&](uint32_t bbyte) {
        char* dst = smem + bbyte + (kp0 * 8) * (B_LD * 2) + n0 * 2;
        uint4 w = breg;
        #pragma unroll
        for (int j = 0; j < 8; j++) {
            uint32_t u01 = 0x64006400u | ((w.x >> (4 * j)) & 0xFu)
                                       | (((w.y >> (4 * j)) & 0xFu) << 16);
            uint32_t u23 = 0x64006400u | ((w.z >> (4 * j)) & 0xFu)
                                       | (((w.w >> (4 * j)) & 0xFu) << 16);
            __half2 h01 = __hmul2(__hsub2(*(__half2*)&u01, hz[0]), hs[0]);
            __half2 h23 = __hmul2(__hsub2(*(__half2*)&u23, hz[1]), hs[1]);
            uint2 v = make_uint2(*(uint32_t*)&h01, *(uint32_t*)&h23);
            *(uint2*)(dst + j * (B_LD * 2)) = v;
        }
    };

    // ---- prologue: stages 0,1 fully staged; regs/consts ready for stage 2 ----
    ldg_consts(0);                 // group of stages 0,1
    ldg_b(0);
    issue_a(0, sbase + 0 * STAGE_BYTES);
    CP_COMMIT();
    issue_a(1, sbase + 1 * STAGE_BYTES);
    CP_COMMIT();
    store_b(0 * STAGE_BYTES + A_STAGE_BYTES);
    ldg_b(1);
    store_b(1 * STAGE_BYTES + A_STAGE_BYTES);
    ldg_consts(1);                 // group of stages 2,3
    ldg_b(2);
    __syncthreads();

    for (int ks = 0; ks < NITER; ks++) {
        const int buf  = ks % NSTAGE;
        const int nbuf = (ks + 2) % NSTAGE;

        // ---- produce stage ks+2 (data/consts prefetched at ks-1) ----
        if (ks + 2 < NITER)
            issue_a(ks + 2, sbase + nbuf * STAGE_BYTES);
        CP_COMMIT();                          // commit every iter (may be empty)
        if (ks + 2 < NITER)
            store_b((uint32_t)(nbuf * STAGE_BYTES + A_STAGE_BYTES));
        if (ks + 3 < NITER) {
            if (ks & 1)
                ldg_consts((ks + 3) >> 1);    // group boundary ahead
            ldg_b(ks + 3);
        }

        CP_WAIT2();                           // group ks committed 2 iters ago

        // ---- compute stage ks ----
        const __half* As = (const __half*)(smem + buf * STAGE_BYTES);
        const __half* Bs = (const __half*)(smem + buf * STAGE_BYTES + A_STAGE_BYTES);
        #pragma unroll
        for (int kk = 0; kk < BK; kk += 16) {
            wmma::fragment<wmma::matrix_a, 16, 16, 16, __half, wmma::row_major> af[4];
            #pragma unroll
            for (int i = 0; i < 4; i++)
                wmma::load_matrix_sync(af[i], As + (wm + i * 16) * A_LD + kk, A_LD);
            #pragma unroll
            for (int j = 0; j < 4; j++) {
                wmma::fragment<wmma::matrix_b, 16, 16, 16, __half, wmma::row_major> bf;
                wmma::load_matrix_sync(bf, Bs + kk * B_LD + wn + j * 16, B_LD);
                #pragma unroll
                for (int i = 0; i < 4; i++)
                    wmma::mma_sync(acc[i][j], af[i], bf, acc[i][j]);
            }
        }

        __syncthreads();                      // STS visibility + buffer reuse
    }

    // ---- epilogue: stage fp32 per warp (16x64 chunks), add bias, write ----
    // buffer 1 (A region, 36KB) last written for stage 61; compute 61 done
    // >= 2 barriers ago, so per-warp reuse is safe.
    float* fbuf = (float*)(smem + STAGE_BYTES) + warp * 16 * C_LD;
    const float* brow = bias + bn + wn;
    #pragma unroll
    for (int i = 0; i < 4; i++) {
        #pragma unroll
        for (int j = 0; j < 4; j++)
            wmma::store_matrix_sync(fbuf + j * 16, acc[i][j], C_LD, wmma::mem_row_major);
        __syncwarp();
        #pragma unroll
        for (int ii = 0; ii < 8; ii++) {
            int idx4 = lane + 32 * ii;          // 256 float4 = 16x64
            int row  = idx4 >> 4;
            int col  = (idx4 & 15) * 4;
            float4 v = *(float4*)(fbuf + row * C_LD + col);
            float4 b4 = *(const float4*)(brow + col);
            v.x += b4.x; v.y += b4.y; v.z += b4.z; v.w += b4.w;
            *(float4*)(out + (size_t)(bm + wm + i * 16 + row) * N_OUT + bn + wn + col) = v;
        }
        __syncwarp();
    }
}

// ---------------------------------------------------------------------------
// Launch.  Inputs: x(f32), qweight(i32), qzeros(i32), scales(f32), g_idx(i32),
//                  bias(f32).  Output f32 [M_TOK, N_OUT].
// ---------------------------------------------------------------------------
extern "C" void kernel_launch(void* const* d_in, const int* in_sizes, int n_in,
                              void* d_out, int out_size)
{
    const float* x       = (const float*)d_in[0];
    const int*   qweight = (const int*)d_in[1];
    const int*   qzeros  = (const int*)d_in[2];
    const float* scales  = (const float*)d_in[3];
    const float* bias    = (const float*)d_in[5];
    float* out = (float*)d_out;

    {
        size_t n4 = (size_t)M_TOK * K_IN / 4;
        convert_x_kernel<<<(unsigned)((n4 + 255) / 256), 256>>>(x);
    }
    {
        cudaFuncSetAttribute(gemm_q4_kernel,
                             cudaFuncAttributeMaxDynamicSharedMemorySize,
                             SMEM_DYN);
        dim3 grid(M_TOK / BM, N_OUT / BN);   // (16, 86), M fastest
        gemm_q4_kernel<<<grid, NTHREADS, SMEM_DYN>>>(qweight, qzeros, scales, bias, out);
    }
}

// round 14
// speedup vs baseline: 1.1425x; 1.1425x over previous
#include <cuda_runtime.h>
#include <cuda_fp16.h>
#include <mma.h>
#include <cstdint>

using namespace nvcuda;

// ---------------------------------------------------------------------------
// Problem constants
// ---------------------------------------------------------------------------
#define M_TOK   4096
#define K_IN    4096
#define N_OUT   11008
#define GROUPSZ 128

// GEMM tiling: 4 warps, warp tile 64x64, 2 CTAs/SM, 3-stage ring
#define BM      128
#define BN      128
#define BK      64
#define NITER   (K_IN / BK)        // 64
#define NTHREADS 128               // 4 warps, warp grid 2(M) x 2(N)
#define NSTAGE  3

#define A_LD    72                 // 64 + 8 pad (halves)
#define B_LD    136                // 128 + 8 pad (halves)
#define C_LD    68                 // 64 + 4 pad (floats), epilogue staging

#define A_STAGE_BYTES (BM * A_LD * 2)      // 18432
#define B_STAGE_BYTES (BK * B_LD * 2)      // 17408
#define STAGE_BYTES   (A_STAGE_BYTES + B_STAGE_BYTES)   // 35840
#define SMEM_DYN      (NSTAGE * STAGE_BYTES)            // 107520 (x2 CTAs = 215KB)

// fp16 x scratch (no allocations allowed)
__device__ __half g_Xh[(size_t)M_TOK * K_IN];

// ---------------------------------------------------------------------------
// Kernel 0: convert x f32 -> f16 (harness materializes jax f16 as f32)
// ---------------------------------------------------------------------------
__global__ void convert_x_kernel(const float* __restrict__ x)
{
    size_t i = ((size_t)blockIdx.x * blockDim.x + threadIdx.x) * 4;
    if (i >= (size_t)M_TOK * K_IN) return;
    float4 v = *(const float4*)(x + i);
    *(__half2*)(g_Xh + i)     = __floats2half2_rn(v.x, v.y);
    *(__half2*)(g_Xh + i + 2) = __floats2half2_rn(v.z, v.w);
}

// ---------------------------------------------------------------------------
// helpers
// ---------------------------------------------------------------------------
__device__ __forceinline__ uint32_t smem_u32(const void* p) {
    uint32_t a;
    asm("{ .reg .u64 t; cvta.to.shared.u64 t, %1; cvt.u32.u64 %0, t; }"
        : "=r"(a) : "l"(p));
    return a;
}
__device__ __forceinline__ void cp_async16(uint32_t saddr, const void* gaddr) {
    asm volatile("cp.async.ca.shared.global [%0], [%1], 16;\n"
                 :: "r"(saddr), "l"(gaddr));
}
#define CP_COMMIT() asm volatile("cp.async.commit_group;\n" ::: "memory")
#define CP_WAIT2()  asm volatile("cp.async.wait_group 2;\n" ::: "memory")

// ---------------------------------------------------------------------------
// Fused 4-bit dequant + HMMA GEMM:  C[M,N] = X[M,K] * dequant(Q)[K,N] + bias
//
// qweight: [K/8, N] int32, nibbles pack K; qzeros: [G, N/8] nibbles pack N;
// scales: [G, N] f32 (fp16 values).
// Dequant via fp16 magic numbers: fp16(0x6400|q) = 1024+q exactly, so
// (u - (1024+z)) * s == fp16(scale) * fp16(q - z) bit-exactly.
//
// R11 pipeline (3-stage ring, produce ks+2, commit/iter + wait_group(2),
// one end-of-iter barrier, 2 CTAs/SM) with ONE change: the produce-side
// ALU work (store_b slices, ldg prefetches) is interleaved IN PROGRAM
// ORDER between the four kk compute chunks. A warp stalled on HMMA
// throughput lets its SMSP partner issue these slices, and vice versa —
// filling the ~600 cyc/stage where both warps previously sat in a lumped
// produce phase. (Unlike R12, this work is independent of the current
// stage's MMAs, so it never blocks tensor issue.)
// ---------------------------------------------------------------------------
__global__ void __launch_bounds__(NTHREADS, 2)
gemm_q4_kernel(const int* __restrict__ qweight,
               const int* __restrict__ qzeros,
               const float* __restrict__ scales,
               const float* __restrict__ bias,
               float* __restrict__ out)
{
    extern __shared__ __align__(16) char smem[];
    const uint32_t sbase = smem_u32(smem);

    const int tid  = threadIdx.x;
    const int warp = tid >> 5;
    const int lane = tid & 31;
    const int bm   = blockIdx.x * BM;   // M fastest: A + qweight stay L2-resident
    const int bn   = blockIdx.y * BN;

    // warp tile: 64x64.  warp grid 2(M) x 2(N)
    const int wm = (warp >> 1) * 64;
    const int wn = (warp & 1) * 64;

    const __half* Xb = g_Xh + (size_t)bm * K_IN;

    // ---- B dequant mapping: 1 kp row x 8 cols per thread ----
    const int n0  = (tid & 15) * 8;          // 0,8,...,120
    const int kp0 = tid >> 4;                // 0..7
    const int o   = bn + n0;                 // multiple of 8: one qzeros word

    wmma::fragment<wmma::accumulator, 16, 16, 16, float> acc[4][4];
    #pragma unroll
    for (int i = 0; i < 4; i++)
        #pragma unroll
        for (int j = 0; j < 4; j++)
            wmma::fill_fragment(acc[i][j], 0.0f);

    uint4   breg[2];          // qweight words: 8 cols of one kp row
    __half2 hz[4];            // (1024+z) pairs for col pairs
    __half2 hs[4];            // scale pairs

    auto ldg_b = [&](int ks) {
        const int* qw = qweight + (size_t)(ks * 8 + kp0) * N_OUT + o;
        breg[0] = *(const uint4*)qw;
        breg[1] = *(const uint4*)(qw + 4);
    };
    auto ldg_consts = [&](int g) {
        uint32_t zw = (uint32_t)qzeros[(size_t)g * (N_OUT / 8) + (o >> 3)];
        #pragma unroll
        for (int k = 0; k < 4; k++) {
            uint32_t z0 = ((zw >> (8 * k))     & 15u) + 1u + 0x6400u;
            uint32_t z1 = ((zw >> (8 * k + 4)) & 15u) + 1u + 0x6400u;
            uint32_t p  = z0 | (z1 << 16);
            hz[k] = *(__half2*)&p;
        }
        float4 s0 = *(const float4*)(scales + (size_t)g * N_OUT + o);
        float4 s1 = *(const float4*)(scales + (size_t)g * N_OUT + o + 4);
        hs[0] = __halves2half2(__float2half_rn(s0.x), __float2half_rn(s0.y));
        hs[1] = __halves2half2(__float2half_rn(s0.z), __float2half_rn(s0.w));
        hs[2] = __halves2half2(__float2half_rn(s1.x), __float2half_rn(s1.y));
        hs[3] = __halves2half2(__float2half_rn(s1.z), __float2half_rn(s1.w));
    };
    auto issue_a = [&](int ks, uint32_t abase) {
        const int k0 = ks * BK;
        #pragma unroll
        for (int i = 0; i < 8; i++) {
            int c = tid + NTHREADS * i;
            int row = c >> 3, cc = c & 7;
            cp_async16(abase + (uint32_t)(row * A_LD + cc * 8) * 2,
                       Xb + (size_t)row * K_IN + k0 + cc * 8);
        }
    };
    // store 4 of the 8 B rows (j = j0..j0+3) — a slice of the dequant
    auto store_b_slice = [&](uint32_t bbyte, int j0) {
        char* dst = smem + bbyte + (kp0 * 8) * (B_LD * 2) + n0 * 2;
        uint4 wa = breg[0], wb = breg[1];
        #pragma unroll
        for (int j = j0; j < j0 + 4; j++) {
            uint32_t u01 = 0x64006400u | ((wa.x >> (4 * j)) & 0xFu)
                                       | (((wa.y >> (4 * j)) & 0xFu) << 16);
            uint32_t u23 = 0x64006400u | ((wa.z >> (4 * j)) & 0xFu)
                                       | (((wa.w >> (4 * j)) & 0xFu) << 16);
            uint32_t u45 = 0x64006400u | ((wb.x >> (4 * j)) & 0xFu)
                                       | (((wb.y >> (4 * j)) & 0xFu) << 16);
            uint32_t u67 = 0x64006400u | ((wb.z >> (4 * j)) & 0xFu)
                                       | (((wb.w >> (4 * j)) & 0xFu) << 16);
            __half2 h01 = __hmul2(__hsub2(*(__half2*)&u01, hz[0]), hs[0]);
            __half2 h23 = __hmul2(__hsub2(*(__half2*)&u23, hz[1]), hs[1]);
            __half2 h45 = __hmul2(__hsub2(*(__half2*)&u45, hz[2]), hs[2]);
            __half2 h67 = __hmul2(__hsub2(*(__half2*)&u67, hz[3]), hs[3]);
            uint4 v = make_uint4(*(uint32_t*)&h01, *(uint32_t*)&h23,
                                 *(uint32_t*)&h45, *(uint32_t*)&h67);
            *(uint4*)(dst + j * (B_LD * 2)) = v;
        }
    };
    // one kk chunk of the 64x64 warp-tile MMA
    auto compute_chunk = [&](const __half* As, const __half* Bs, int kk) {
        wmma::fragment<wmma::matrix_a, 16, 16, 16, __half, wmma::row_major> af[4];
        #pragma unroll
        for (int i = 0; i < 4; i++)
            wmma::load_matrix_sync(af[i], As + (wm + i * 16) * A_LD + kk, A_LD);
        #pragma unroll
        for (int j = 0; j < 4; j++) {
            wmma::fragment<wmma::matrix_b, 16, 16, 16, __half, wmma::row_major> bf;
            wmma::load_matrix_sync(bf, Bs + kk * B_LD + wn + j * 16, B_LD);
            #pragma unroll
            for (int i = 0; i < 4; i++)
                wmma::mma_sync(acc[i][j], af[i], bf, acc[i][j]);
        }
    };

    // ---- prologue: stages 0,1 fully staged; regs/consts ready for stage 2 ----
    ldg_consts(0);                 // group of stages 0,1
    ldg_b(0);
    issue_a(0, sbase + 0 * STAGE_BYTES);
    CP_COMMIT();
    issue_a(1, sbase + 1 * STAGE_BYTES);
    CP_COMMIT();
    store_b_slice(0 * STAGE_BYTES + A_STAGE_BYTES, 0);
    store_b_slice(0 * STAGE_BYTES + A_STAGE_BYTES, 4);
    ldg_b(1);
    store_b_slice(1 * STAGE_BYTES + A_STAGE_BYTES, 0);
    store_b_slice(1 * STAGE_BYTES + A_STAGE_BYTES, 4);
    ldg_consts(1);                 // group of stages 2,3
    ldg_b(2);
    __syncthreads();

    for (int ks = 0; ks < NITER; ks++) {
        const int buf  = ks % NSTAGE;
        const int nbuf = (ks + 2) % NSTAGE;
        const bool produce = (ks + 2 < NITER);
        const uint32_t nb_byte = (uint32_t)(nbuf * STAGE_BYTES + A_STAGE_BYTES);

        if (produce)
            issue_a(ks + 2, sbase + nbuf * STAGE_BYTES);
        CP_COMMIT();                          // commit every iter
        CP_WAIT2();                           // stage-ks group: 2 iters old

        const __half* As = (const __half*)(smem + buf * STAGE_BYTES);
        const __half* Bs = (const __half*)(smem + buf * STAGE_BYTES + A_STAGE_BYTES);

        // compute interleaved (in program order) with produce slices
        compute_chunk(As, Bs, 0);
        if (produce) store_b_slice(nb_byte, 0);
        compute_chunk(As, Bs, 16);
        if (produce) store_b_slice(nb_byte, 4);
        compute_chunk(As, Bs, 32);
        if (ks + 3 < NITER) {
            if (ks & 1)
                ldg_consts((ks + 3) >> 1);    // group boundary ahead
            ldg_b(ks + 3);
        }
        compute_chunk(As, Bs, 48);

        __syncthreads();                      // STS visibility + buffer reuse
    }

    // ---- epilogue: stage fp32 per warp (16x64 chunks), add bias, write ----
    float* fbuf = (float*)(smem + STAGE_BYTES) + warp * 16 * C_LD;
    const float* brow = bias + bn + wn;
    #pragma unroll
    for (int i = 0; i < 4; i++) {
        #pragma unroll
        for (int j = 0; j < 4; j++)
            wmma::store_matrix_sync(fbuf + j * 16, acc[i][j], C_LD, wmma::mem_row_major);
        __syncwarp();
        #pragma unroll
        for (int ii = 0; ii < 8; ii++) {
            int idx4 = lane + 32 * ii;          // 256 float4 = 16x64
            int row  = idx4 >> 4;
            int col  = (idx4 & 15) * 4;
            float4 v = *(float4*)(fbuf + row * C_LD + col);
            float4 b4 = *(const float4*)(brow + col);
            v.x += b4.x; v.y += b4.y; v.z += b4.z; v.w += b4.w;
            *(float4*)(out + (size_t)(bm + wm + i * 16 + row) * N_OUT + bn + wn + col) = v;
        }
        __syncwarp();
    }
}

// ---------------------------------------------------------------------------
// Launch.  Inputs: x(f32), qweight(i32), qzeros(i32), scales(f32), g_idx(i32),
//                  bias(f32).  Output f32 [M_TOK, N_OUT].
// ---------------------------------------------------------------------------
extern "C" void kernel_launch(void* const* d_in, const int* in_sizes, int n_in,
                              void* d_out, int out_size)
{
    const float* x       = (const float*)d_in[0];
    const int*   qweight = (const int*)d_in[1];
    const int*   qzeros  = (const int*)d_in[2];
    const float* scales  = (const float*)d_in[3];
    const float* bias    = (const float*)d_in[5];
    float* out = (float*)d_out;

    {
        size_t n4 = (size_t)M_TOK * K_IN / 4;
        convert_x_kernel<<<(unsigned)((n4 + 255) / 256), 256>>>(x);
    }
    {
        cudaFuncSetAttribute(gemm_q4_kernel,
                             cudaFuncAttributeMaxDynamicSharedMemorySize,
                             SMEM_DYN);
        dim3 grid(M_TOK / BM, N_OUT / BN);   // (32, 86), M fastest
        gemm_q4_kernel<<<grid, NTHREADS, SMEM_DYN>>>(qweight, qzeros, scales, bias, out);
    }
}

// round 15
// speedup vs baseline: 1.1994x; 1.0498x over previous
#include <cuda_runtime.h>
#include <cuda_fp16.h>
#include <mma.h>
#include <cstdint>

using namespace nvcuda;

// ---------------------------------------------------------------------------
// Problem constants
// ---------------------------------------------------------------------------
#define M_TOK   4096
#define K_IN    4096
#define N_OUT   11008
#define GROUPSZ 128

// GEMM tiling: 4 warps, warp tile 64x64, 2 CTAs/SM, 3-stage ring
#define BM      128
#define BN      128
#define BK      64
#define NITER   (K_IN / BK)        // 64
#define NTHREADS 128               // 4 warps, warp grid 2(M) x 2(N)
#define NSTAGE  3

#define A_LD    72                 // 64 + 8 pad (halves)
#define B_LD    136                // 128 + 8 pad (halves)
#define C_LD    68                 // 64 + 4 pad (floats), epilogue staging

#define A_STAGE_BYTES (BM * A_LD * 2)      // 18432
#define B_STAGE_BYTES (BK * B_LD * 2)      // 17408
#define STAGE_BYTES   (A_STAGE_BYTES + B_STAGE_BYTES)   // 35840
#define SMEM_DYN      (NSTAGE * STAGE_BYTES)            // 107520 (x2 CTAs = 215KB)

// fp16 x scratch (no allocations allowed)
__device__ __half g_Xh[(size_t)M_TOK * K_IN];

// ---------------------------------------------------------------------------
// Kernel 0: convert x f32 -> f16 (harness materializes jax f16 as f32)
// ---------------------------------------------------------------------------
__global__ void convert_x_kernel(const float* __restrict__ x)
{
    size_t i = ((size_t)blockIdx.x * blockDim.x + threadIdx.x) * 4;
    if (i >= (size_t)M_TOK * K_IN) return;
    float4 v = *(const float4*)(x + i);
    *(__half2*)(g_Xh + i)     = __floats2half2_rn(v.x, v.y);
    *(__half2*)(g_Xh + i + 2) = __floats2half2_rn(v.z, v.w);
}

// ---------------------------------------------------------------------------
// helpers
// ---------------------------------------------------------------------------
__device__ __forceinline__ uint32_t smem_u32(const void* p) {
    uint32_t a;
    asm("{ .reg .u64 t; cvta.to.shared.u64 t, %1; cvt.u32.u64 %0, t; }"
        : "=r"(a) : "l"(p));
    return a;
}
__device__ __forceinline__ void cp_async16(uint32_t saddr, const void* gaddr) {
    asm volatile("cp.async.ca.shared.global [%0], [%1], 16;\n"
                 :: "r"(saddr), "l"(gaddr));
}
#define CP_COMMIT() asm volatile("cp.async.commit_group;\n" ::: "memory")
#define CP_WAIT2()  asm volatile("cp.async.wait_group 2;\n" ::: "memory")
#define BAR_SYNC(id, cnt) \
    asm volatile("bar.sync %0, %1;" :: "r"(id), "r"(cnt) : "memory")
#define BAR_ARRIVE(id, cnt) \
    asm volatile("bar.arrive %0, %1;" :: "r"(id), "r"(cnt) : "memory")

// ---------------------------------------------------------------------------
// Fused 4-bit dequant + HMMA GEMM:  C[M,N] = X[M,K] * dequant(Q)[K,N] + bias
//
// qweight: [K/8, N] int32, nibbles pack K; qzeros: [G, N/8] nibbles pack N;
// scales: [G, N] f32 (fp16 values).
// Dequant via fp16 magic numbers: fp16(0x6400|q) = 1024+q exactly, so
// (u - (1024+z)) * s == fp16(scale) * fp16(q - z) bit-exactly.
//
// R11 pipeline (3-stage ring, produce ks+2, commit/iter + wait_group(2),
// 2 CTAs/SM) with the end-of-iter __syncthreads split into a named-barrier
// arrive/sync pair: arrive(1,256) after the MMA chain (all LDSM of the
// stage are provably complete: the issued mma.syncs depend on them), and
// sync(1,256) at the next iter's top before any SMEM writes. A warp's
// ~2000-cyc MMA tail now overlaps the next stage's produce instead of
// serializing behind a full execution barrier. Rounds: arrives@k pair with
// syncs@k+1, 128+128=256, uniform control flow keeps counts aligned.
// ---------------------------------------------------------------------------
__global__ void __launch_bounds__(NTHREADS, 2)
gemm_q4_kernel(const int* __restrict__ qweight,
               const int* __restrict__ qzeros,
               const float* __restrict__ scales,
               const float* __restrict__ bias,
               float* __restrict__ out)
{
    extern __shared__ __align__(16) char smem[];
    const uint32_t sbase = smem_u32(smem);

    const int tid  = threadIdx.x;
    const int warp = tid >> 5;
    const int lane = tid & 31;
    const int bm   = blockIdx.x * BM;   // M fastest: A + qweight stay L2-resident
    const int bn   = blockIdx.y * BN;

    // warp tile: 64x64.  warp grid 2(M) x 2(N)
    const int wm = (warp >> 1) * 64;
    const int wn = (warp & 1) * 64;

    const __half* Xb = g_Xh + (size_t)bm * K_IN;

    // ---- B dequant mapping: 1 kp row x 8 cols per thread ----
    const int n0  = (tid & 15) * 8;          // 0,8,...,120
    const int kp0 = tid >> 4;                // 0..7
    const int o   = bn + n0;                 // multiple of 8: one qzeros word

    wmma::fragment<wmma::accumulator, 16, 16, 16, float> acc[4][4];
    #pragma unroll
    for (int i = 0; i < 4; i++)
        #pragma unroll
        for (int j = 0; j < 4; j++)
            wmma::fill_fragment(acc[i][j], 0.0f);

    uint4   breg[2];          // qweight words: 8 cols of one kp row
    __half2 hz[4];            // (1024+z) pairs for col pairs
    __half2 hs[4];            // scale pairs

    auto ldg_b = [&](int ks) {
        const int* qw = qweight + (size_t)(ks * 8 + kp0) * N_OUT + o;
        breg[0] = *(const uint4*)qw;
        breg[1] = *(const uint4*)(qw + 4);
    };
    auto ldg_consts = [&](int g) {
        uint32_t zw = (uint32_t)qzeros[(size_t)g * (N_OUT / 8) + (o >> 3)];
        #pragma unroll
        for (int k = 0; k < 4; k++) {
            uint32_t z0 = ((zw >> (8 * k))     & 15u) + 1u + 0x6400u;
            uint32_t z1 = ((zw >> (8 * k + 4)) & 15u) + 1u + 0x6400u;
            uint32_t p  = z0 | (z1 << 16);
            hz[k] = *(__half2*)&p;
        }
        float4 s0 = *(const float4*)(scales + (size_t)g * N_OUT + o);
        float4 s1 = *(const float4*)(scales + (size_t)g * N_OUT + o + 4);
        hs[0] = __halves2half2(__float2half_rn(s0.x), __float2half_rn(s0.y));
        hs[1] = __halves2half2(__float2half_rn(s0.z), __float2half_rn(s0.w));
        hs[2] = __halves2half2(__float2half_rn(s1.x), __float2half_rn(s1.y));
        hs[3] = __halves2half2(__float2half_rn(s1.z), __float2half_rn(s1.w));
    };
    auto issue_a = [&](int ks, uint32_t abase) {
        const int k0 = ks * BK;
        #pragma unroll
        for (int i = 0; i < 8; i++) {
            int c = tid + NTHREADS * i;
            int row = c >> 3, cc = c & 7;
            cp_async16(abase + (uint32_t)(row * A_LD + cc * 8) * 2,
                       Xb + (size_t)row * K_IN + k0 + cc * 8);
        }
    };
    auto store_b = [&](uint32_t bbyte) {
        char* dst = smem + bbyte + (kp0 * 8) * (B_LD * 2) + n0 * 2;
        uint4 wa = breg[0], wb = breg[1];
        #pragma unroll
        for (int j = 0; j < 8; j++) {
            uint32_t u01 = 0x64006400u | ((wa.x >> (4 * j)) & 0xFu)
                                       | (((wa.y >> (4 * j)) & 0xFu) << 16);
            uint32_t u23 = 0x64006400u | ((wa.z >> (4 * j)) & 0xFu)
                                       | (((wa.w >> (4 * j)) & 0xFu) << 16);
            uint32_t u45 = 0x64006400u | ((wb.x >> (4 * j)) & 0xFu)
                                       | (((wb.y >> (4 * j)) & 0xFu) << 16);
            uint32_t u67 = 0x64006400u | ((wb.z >> (4 * j)) & 0xFu)
                                       | (((wb.w >> (4 * j)) & 0xFu) << 16);
            __half2 h01 = __hmul2(__hsub2(*(__half2*)&u01, hz[0]), hs[0]);
            __half2 h23 = __hmul2(__hsub2(*(__half2*)&u23, hz[1]), hs[1]);
            __half2 h45 = __hmul2(__hsub2(*(__half2*)&u45, hz[2]), hs[2]);
            __half2 h67 = __hmul2(__hsub2(*(__half2*)&u67, hz[3]), hs[3]);
            uint4 v = make_uint4(*(uint32_t*)&h01, *(uint32_t*)&h23,
                                 *(uint32_t*)&h45, *(uint32_t*)&h67);
            *(uint4*)(dst + j * (B_LD * 2)) = v;
        }
    };

    // ---- prologue: stages 0,1 fully staged; regs/consts ready for stage 2 ----
    ldg_consts(0);                 // group of stages 0,1
    ldg_b(0);
    issue_a(0, sbase + 0 * STAGE_BYTES);
    CP_COMMIT();
    issue_a(1, sbase + 1 * STAGE_BYTES);
    CP_COMMIT();
    store_b(0 * STAGE_BYTES + A_STAGE_BYTES);
    ldg_b(1);
    store_b(1 * STAGE_BYTES + A_STAGE_BYTES);
    ldg_consts(1);                 // group of stages 2,3
    ldg_b(2);
    __syncthreads();

    for (int ks = 0; ks < NITER; ks++) {
        const int buf  = ks % NSTAGE;
        const int nbuf = (ks + 2) % NSTAGE;
        const bool produce = (ks + 2 < NITER);

        // gate SMEM writes on readers of the target buffer having finished
        // their loads (arrive@ks-1). Skipped at ks=0 (prologue __syncthreads
        // covers it) and at non-producing tail iters (no writes happen).
        if (produce && ks > 0)
            BAR_SYNC(1, 2 * NTHREADS);

        if (produce)
            issue_a(ks + 2, sbase + nbuf * STAGE_BYTES);
        CP_COMMIT();                          // commit every iter (may be empty)
        if (produce)
            store_b((uint32_t)(nbuf * STAGE_BYTES + A_STAGE_BYTES));
        if (ks + 3 < NITER) {
            if (ks & 1)
                ldg_consts((ks + 3) >> 1);    // group boundary ahead
            ldg_b(ks + 3);
        }

        CP_WAIT2();                           // group ks committed 2 iters ago

        // ---- compute stage ks ----
        const __half* As = (const __half*)(smem + buf * STAGE_BYTES);
        const __half* Bs = (const __half*)(smem + buf * STAGE_BYTES + A_STAGE_BYTES);
        #pragma unroll
        for (int kk = 0; kk < BK; kk += 16) {
            wmma::fragment<wmma::matrix_a, 16, 16, 16, __half, wmma::row_major> af[4];
            #pragma unroll
            for (int i = 0; i < 4; i++)
                wmma::load_matrix_sync(af[i], As + (wm + i * 16) * A_LD + kk, A_LD);
            #pragma unroll
            for (int j = 0; j < 4; j++) {
                wmma::fragment<wmma::matrix_b, 16, 16, 16, __half, wmma::row_major> bf;
                wmma::load_matrix_sync(bf, Bs + kk * B_LD + wn + j * 16, B_LD);
                #pragma unroll
                for (int i = 0; i < 4; i++)
                    wmma::mma_sync(acc[i][j], af[i], bf, acc[i][j]);
            }
        }

        // all LDSM of this stage are complete (the issued mma.syncs above
        // depend on them); signal readers-done without blocking on MMA drain
        BAR_ARRIVE(1, 2 * NTHREADS);
    }

    __syncthreads();   // full barrier before smem reuse by the epilogue

    // ---- epilogue: stage fp32 per warp (16x64 chunks), add bias, write ----
    float* fbuf = (float*)(smem + STAGE_BYTES) + warp * 16 * C_LD;
    const float* brow = bias + bn + wn;
    #pragma unroll
    for (int i = 0; i < 4; i++) {
        #pragma unroll
        for (int j = 0; j < 4; j++)
            wmma::store_matrix_sync(fbuf + j * 16, acc[i][j], C_LD, wmma::mem_row_major);
        __syncwarp();
        #pragma unroll
        for (int ii = 0; ii < 8; ii++) {
            int idx4 = lane + 32 * ii;          // 256 float4 = 16x64
            int row  = idx4 >> 4;
            int col  = (idx4 & 15) * 4;
            float4 v = *(float4*)(fbuf + row * C_LD + col);
            float4 b4 = *(const float4*)(brow + col);
            v.x += b4.x; v.y += b4.y; v.z += b4.z; v.w += b4.w;
            *(float4*)(out + (size_t)(bm + wm + i * 16 + row) * N_OUT + bn + wn + col) = v;
        }
        __syncwarp();
    }
}

// ---------------------------------------------------------------------------
// Launch.  Inputs: x(f32), qweight(i32), qzeros(i32), scales(f32), g_idx(i32),
//                  bias(f32).  Output f32 [M_TOK, N_OUT].
// ---------------------------------------------------------------------------
extern "C" void kernel_launch(void* const* d_in, const int* in_sizes, int n_in,
                              void* d_out, int out_size)
{
    const float* x       = (const float*)d_in[0];
    const int*   qweight = (const int*)d_in[1];
    const int*   qzeros  = (const int*)d_in[2];
    const float* scales  = (const float*)d_in[3];
    const float* bias    = (const float*)d_in[5];
    float* out = (float*)d_out;

    {
        size_t n4 = (size_t)M_TOK * K_IN / 4;
        convert_x_kernel<<<(unsigned)((n4 + 255) / 256), 256>>>(x);
    }
    {
        cudaFuncSetAttribute(gemm_q4_kernel,
                             cudaFuncAttributeMaxDynamicSharedMemorySize,
                             SMEM_DYN);
        dim3 grid(M_TOK / BM, N_OUT / BN);   // (32, 86), M fastest
        gemm_q4_kernel<<<grid, NTHREADS, SMEM_DYN>>>(qweight, qzeros, scales, bias, out);
    }
}